// round 2
// baseline (speedup 1.0000x reference)
#include <cuda_runtime.h>
#include <math_constants.h>

#define NB   1024
#define NH   16384
#define SDIM 32
#define HID  64
#define NG   10
#define NK   4
#define NA   8
#define GA   80

#define QT   32
#define KT   64
#define LPAD 66
#define ATHREADS 256

// Scratch (no cudaMalloc allowed)
__device__ float g_enc_h[NK * NH * HID];   // [k][h][d]
__device__ float g_enc_s[NK * NB * HID];   // [k][b][d]
__device__ float g_O[NK * NB * GA];        // [k][b][ga]

// Packed dual-fp32 FMA (sm_100+ f32x2 pipe, 2x FFMA throughput)
__device__ __forceinline__ float2 ffma2(float2 a, float2 b, float2 c) {
    unsigned long long ua = *reinterpret_cast<unsigned long long*>(&a);
    unsigned long long ub = *reinterpret_cast<unsigned long long*>(&b);
    unsigned long long uc = *reinterpret_cast<unsigned long long*>(&c);
    unsigned long long ud;
    asm("fma.rn.f32x2 %0, %1, %2, %3;" : "=l"(ud) : "l"(ua), "l"(ub), "l"(uc));
    return *reinterpret_cast<float2*>(&ud);
}

// ---------------------------------------------------------------------------
// Encoder: x[nrows,32] -> out[k][nrows][64], 3x (Linear+ReLU), per-k weights.
// Block: 256 threads = 4 rows x 64 neurons, 64 rows per block.
// Weight columns register-cached as float2 pairs; x/h read via smem broadcast.
// ---------------------------------------------------------------------------
__global__ __launch_bounds__(256) void encoder_kernel(
    const float* __restrict__ x, float* __restrict__ out, int nrows,
    const float* __restrict__ W0, const float* __restrict__ b0,
    const float* __restrict__ W1, const float* __restrict__ b1,
    const float* __restrict__ W2, const float* __restrict__ b2)
{
    const int k    = blockIdx.y;
    const int row0 = blockIdx.x * 64;
    const int tid  = threadIdx.x;
    const int o    = tid & 63;   // neuron
    const int rr   = tid >> 6;   // row phase 0..3

    __shared__ float xs[64 * SDIM];
    __shared__ float hs0[64 * HID];
    __shared__ float hs1[64 * HID];

    for (int i = tid; i < 64 * SDIM; i += 256)
        xs[i] = x[(size_t)row0 * SDIM + i];
    __syncthreads();

    // ---- layer 0: 32 -> 64 ----
    {
        float2 w[SDIM / 2];
        const float* Wp = W0 + (size_t)k * SDIM * HID + o;
        #pragma unroll
        for (int i = 0; i < SDIM / 2; i++)
            w[i] = make_float2(Wp[(2 * i) * HID], Wp[(2 * i + 1) * HID]);
        const float bias = b0[k * HID + o];
        #pragma unroll 4
        for (int r = rr; r < 64; r += 4) {
            const float2* xr = reinterpret_cast<const float2*>(xs + r * SDIM);
            float2 acc = make_float2(0.f, 0.f);
            #pragma unroll
            for (int i = 0; i < SDIM / 2; i++) acc = ffma2(xr[i], w[i], acc);
            hs0[r * HID + o] = fmaxf(acc.x + acc.y + bias, 0.f);
        }
    }
    __syncthreads();

    // ---- layer 1: 64 -> 64 ----
    {
        float2 w[HID / 2];
        const float* Wp = W1 + (size_t)k * HID * HID + o;
        #pragma unroll
        for (int i = 0; i < HID / 2; i++)
            w[i] = make_float2(Wp[(2 * i) * HID], Wp[(2 * i + 1) * HID]);
        const float bias = b1[k * HID + o];
        #pragma unroll 4
        for (int r = rr; r < 64; r += 4) {
            const float2* hr = reinterpret_cast<const float2*>(hs0 + r * HID);
            float2 acc = make_float2(0.f, 0.f);
            #pragma unroll
            for (int i = 0; i < HID / 2; i++) acc = ffma2(hr[i], w[i], acc);
            hs1[r * HID + o] = fmaxf(acc.x + acc.y + bias, 0.f);
        }
    }
    __syncthreads();

    // ---- layer 2: 64 -> 64, write to gmem ----
    {
        float2 w[HID / 2];
        const float* Wp = W2 + (size_t)k * HID * HID + o;
        #pragma unroll
        for (int i = 0; i < HID / 2; i++)
            w[i] = make_float2(Wp[(2 * i) * HID], Wp[(2 * i + 1) * HID]);
        const float bias = b2[k * HID + o];
        #pragma unroll 4
        for (int r = rr; r < 64; r += 4) {
            const float2* hr = reinterpret_cast<const float2*>(hs1 + r * HID);
            float2 acc = make_float2(0.f, 0.f);
            #pragma unroll
            for (int i = 0; i < HID / 2; i++) acc = ffma2(hr[i], w[i], acc);
            out[(size_t)k * nrows * HID + (size_t)(row0 + r) * HID + o] =
                fmaxf(acc.x + acc.y + bias, 0.f);
        }
    }
}

// ---------------------------------------------------------------------------
// Flash attention: per (k, 32-query tile) block streams 16384 keys in tiles
// of 64. Q=enc_s, K=enc_h, V=joint_action_history[H][80] (shared over k).
// Thread (qq,sub): queries {2qq,2qq+1}; scores for keys {sub,sub+16,+32,+48};
// PV for a = sub*5..sub*5+4. Tiles padded to stride 66 for bank-free access.
// ---------------------------------------------------------------------------
__global__ __launch_bounds__(ATHREADS) void attn_kernel(const float* __restrict__ V)
{
    extern __shared__ float sm[];
    float* Qs = sm;                         // QT*64
    float* Ks = Qs + QT * 64;               // KT*LPAD
    float* Vs = Ks + KT * LPAD;             // GA*LPAD (transposed: [a][j])
    float* Ps = Vs + GA * LPAD;             // QT*64

    const int k   = blockIdx.y;
    const int q0  = blockIdx.x * QT;
    const int tid = threadIdx.x;
    const int qq  = tid >> 4;   // 0..15 -> queries 2qq, 2qq+1
    const int sub = tid & 15;

    const float* encs = g_enc_s + ((size_t)k * NB + q0) * HID;
    for (int i = tid; i < QT * HID; i += ATHREADS)
        Qs[i] = encs[i];

    float m0 = -CUDART_INF_F, m1 = -CUDART_INF_F;
    float l0 = 0.f, l1 = 0.f;
    float2 acc0[5], acc1[5];
    #pragma unroll
    for (int i = 0; i < 5; i++) {
        acc0[i] = make_float2(0.f, 0.f);
        acc1[i] = make_float2(0.f, 0.f);
    }

    const float2* KG = reinterpret_cast<const float2*>(g_enc_h + (size_t)k * NH * HID);

    for (int key0 = 0; key0 < NH; key0 += KT) {
        __syncthreads();   // previous PV must finish before tile overwrite

        // Load K tile (64x64 f32 as float2, padded stride 33 float2)
        {
            const float2* kg = KG + (size_t)key0 * (HID / 2);
            float2* Ks2 = reinterpret_cast<float2*>(Ks);
            #pragma unroll
            for (int t = 0; t < (KT * HID / 2) / ATHREADS; t++) {
                int i = tid + t * ATHREADS;
                Ks2[(i >> 5) * (LPAD / 2) + (i & 31)] = kg[i];
            }
            // Load V tile transposed: Vs[a][j] = V[key0+j][a]
            const float* vg = V + (size_t)key0 * GA;
            #pragma unroll
            for (int t = 0; t < (KT * GA) / ATHREADS; t++) {
                int i = tid + t * ATHREADS;
                int j = i / GA;
                int a = i - j * GA;
                Vs[a * LPAD + j] = vg[i];
            }
        }
        __syncthreads();

        // ---- scores: 2 queries x 4 keys per thread (dual-fp32 dot) ----
        float2 d0[4], d1[4];
        #pragma unroll
        for (int jj = 0; jj < 4; jj++) {
            d0[jj] = make_float2(0.f, 0.f);
            d1[jj] = make_float2(0.f, 0.f);
        }
        const float2* qa2 = reinterpret_cast<const float2*>(Qs + (2 * qq) * 64);
        const float2* qb2 = reinterpret_cast<const float2*>(Qs + (2 * qq + 1) * 64);
        #pragma unroll 8
        for (int d2 = 0; d2 < 32; d2++) {
            float2 qa = qa2[d2], qb = qb2[d2];
            #pragma unroll
            for (int jj = 0; jj < 4; jj++) {
                float2 kk = *reinterpret_cast<const float2*>(
                    Ks + (sub + 16 * jj) * LPAD + 2 * d2);
                d0[jj] = ffma2(qa, kk, d0[jj]);
                d1[jj] = ffma2(qb, kk, d1[jj]);
            }
        }
        float s0[4], s1[4];
        #pragma unroll
        for (int jj = 0; jj < 4; jj++) {
            s0[jj] = d0[jj].x + d0[jj].y;
            s1[jj] = d1[jj].x + d1[jj].y;
        }

        // ---- online softmax (16-lane group reductions) ----
        float tm0 = fmaxf(fmaxf(s0[0], s0[1]), fmaxf(s0[2], s0[3]));
        float tm1 = fmaxf(fmaxf(s1[0], s1[1]), fmaxf(s1[2], s1[3]));
        #pragma unroll
        for (int off = 8; off > 0; off >>= 1) {
            tm0 = fmaxf(tm0, __shfl_xor_sync(0xffffffffu, tm0, off));
            tm1 = fmaxf(tm1, __shfl_xor_sync(0xffffffffu, tm1, off));
        }
        float nm0 = fmaxf(m0, tm0), nm1 = fmaxf(m1, tm1);
        float c0 = __expf(m0 - nm0), c1 = __expf(m1 - nm1);
        m0 = nm0; m1 = nm1;

        float p0[4], p1[4];
        float ts0 = 0.f, ts1 = 0.f;
        #pragma unroll
        for (int jj = 0; jj < 4; jj++) {
            p0[jj] = __expf(s0[jj] - m0);
            p1[jj] = __expf(s1[jj] - m1);
            ts0 += p0[jj];
            ts1 += p1[jj];
        }
        #pragma unroll
        for (int off = 8; off > 0; off >>= 1) {
            ts0 += __shfl_xor_sync(0xffffffffu, ts0, off);
            ts1 += __shfl_xor_sync(0xffffffffu, ts1, off);
        }
        l0 = l0 * c0 + ts0;
        l1 = l1 * c1 + ts1;

        #pragma unroll
        for (int jj = 0; jj < 4; jj++) {
            Ps[(2 * qq) * 64 + sub + 16 * jj]     = p0[jj];
            Ps[(2 * qq + 1) * 64 + sub + 16 * jj] = p1[jj];
        }
        #pragma unroll
        for (int i = 0; i < 5; i++) {
            acc0[i].x *= c0; acc0[i].y *= c0;
            acc1[i].x *= c1; acc1[i].y *= c1;
        }
        __syncthreads();

        // ---- PV: 2 queries x 5 output dims per thread ----
        const float2* P0 = reinterpret_cast<const float2*>(Ps + (2 * qq) * 64);
        const float2* P1 = reinterpret_cast<const float2*>(Ps + (2 * qq + 1) * 64);
        #pragma unroll 8
        for (int j2 = 0; j2 < 32; j2++) {
            float2 pa = P0[j2], pb = P1[j2];
            #pragma unroll
            for (int i = 0; i < 5; i++) {
                float2 vv = *reinterpret_cast<const float2*>(
                    Vs + (sub * 5 + i) * LPAD + 2 * j2);
                acc0[i] = ffma2(pa, vv, acc0[i]);
                acc1[i] = ffma2(pb, vv, acc1[i]);
            }
        }
    }

    // ---- epilogue: normalize, write per-k attention output ----
    float inv0 = 1.f / l0, inv1 = 1.f / l1;
    float* O0 = g_O + ((size_t)k * NB + (q0 + 2 * qq)) * GA;
    #pragma unroll
    for (int i = 0; i < 5; i++) {
        O0[sub * 5 + i]      = (acc0[i].x + acc0[i].y) * inv0;
        O0[GA + sub * 5 + i] = (acc1[i].x + acc1[i].y) * inv1;
    }
}

// ---------------------------------------------------------------------------
// Combine: out[b,g,a] = sum_k softmax_k(assign[g,:]) * O[k,b,g*8+a]
// ---------------------------------------------------------------------------
__global__ __launch_bounds__(256) void combine_kernel(
    const float* __restrict__ assign, float* __restrict__ out)
{
    int idx = blockIdx.x * 256 + threadIdx.x;
    if (idx >= NB * GA) return;
    int b  = idx / GA;
    int ga = idx - b * GA;
    int g  = ga >> 3;
    float a0 = __ldg(assign + g * NK + 0);
    float a1 = __ldg(assign + g * NK + 1);
    float a2 = __ldg(assign + g * NK + 2);
    float a3 = __ldg(assign + g * NK + 3);
    float mx = fmaxf(fmaxf(a0, a1), fmaxf(a2, a3));
    float e0 = __expf(a0 - mx), e1 = __expf(a1 - mx);
    float e2 = __expf(a2 - mx), e3 = __expf(a3 - mx);
    float inv = 1.f / (e0 + e1 + e2 + e3);
    float r = e0 * g_O[(size_t)(0 * NB + b) * GA + ga]
            + e1 * g_O[(size_t)(1 * NB + b) * GA + ga]
            + e2 * g_O[(size_t)(2 * NB + b) * GA + ga]
            + e3 * g_O[(size_t)(3 * NB + b) * GA + ga];
    out[idx] = r * inv;
}

// ---------------------------------------------------------------------------
extern "C" void kernel_launch(void* const* d_in, const int* in_sizes, int n_in,
                              void* d_out, int out_size)
{
    (void)in_sizes; (void)n_in; (void)out_size;
    const float* state  = (const float*)d_in[0];
    const float* hist   = (const float*)d_in[1];
    const float* jah    = (const float*)d_in[2];
    const float* W0 = (const float*)d_in[3];
    const float* b0 = (const float*)d_in[4];
    const float* W1 = (const float*)d_in[5];
    const float* b1 = (const float*)d_in[6];
    const float* W2 = (const float*)d_in[7];
    const float* b2 = (const float*)d_in[8];
    const float* assign = (const float*)d_in[9];
    float* out = (float*)d_out;

    float* enc_h_p = nullptr;
    float* enc_s_p = nullptr;
    cudaGetSymbolAddress((void**)&enc_h_p, g_enc_h);
    cudaGetSymbolAddress((void**)&enc_s_p, g_enc_s);

    encoder_kernel<<<dim3(NH / 64, NK), 256>>>(hist, enc_h_p, NH,
                                               W0, b0, W1, b1, W2, b2);
    encoder_kernel<<<dim3(NB / 64, NK), 256>>>(state, enc_s_p, NB,
                                               W0, b0, W1, b1, W2, b2);

    const int smem_bytes =
        (QT * 64 + KT * LPAD + GA * LPAD + QT * 64) * (int)sizeof(float);
    cudaFuncSetAttribute(attn_kernel,
                         cudaFuncAttributeMaxDynamicSharedMemorySize, smem_bytes);
    attn_kernel<<<dim3(NB / QT, NK), ATHREADS, smem_bytes>>>(jah);

    combine_kernel<<<(NB * GA + 255) / 256, 256>>>(assign, out);
}

// round 5
// speedup vs baseline: 1.7615x; 1.7615x over previous
#include <cuda_runtime.h>
#include <math_constants.h>

#define NB   1024
#define NH   16384
#define SDIM 32
#define HID  64
#define NG   10
#define NK   4
#define GA   80

#define QT   32            // queries per block
#define KT   128           // keys per tile
#define KROW 132           // padded row stride (floats) for K/V/P smem tiles
#define QROW 36            // padded row stride for Q tile
#define NTILES (NH / KT)   // 128
#define ATHREADS 256

// Scratch (no cudaMalloc allowed)
__device__ float g_enc_hT[NK * HID * NH];   // [k][d][h]
__device__ float g_enc_sT[NK * HID * NB];   // [k][d][b]
__device__ float g_VT[GA * NH];             // [a][j]
__device__ float g_O[NK * NB * GA];         // [k][b][ga]

// Packed dual-fp32 FMA (sm_103a f32x2 pipe, 2x FFMA throughput)
__device__ __forceinline__ float2 ffma2(float2 a, float2 b, float2 c) {
    unsigned long long ua = *reinterpret_cast<unsigned long long*>(&a);
    unsigned long long ub = *reinterpret_cast<unsigned long long*>(&b);
    unsigned long long uc = *reinterpret_cast<unsigned long long*>(&c);
    unsigned long long ud;
    asm("fma.rn.f32x2 %0, %1, %2, %3;" : "=l"(ud) : "l"(ua), "l"(ub), "l"(uc));
    return *reinterpret_cast<float2*>(&ud);
}

__device__ __forceinline__ void cp16(float* dst, const float* src) {
    unsigned s = (unsigned)__cvta_generic_to_shared(dst);
    asm volatile("cp.async.cg.shared.global [%0], [%1], 16;\n" :: "r"(s), "l"(src));
}

// ---------------------------------------------------------------------------
// Encoder: x[nrows,32] -> outT[k][d][nrows] (TRANSPOSED), 3x (Linear+ReLU).
// Block: 256 threads = 4 row-phases x 64 neurons, 64 rows per block.
// ---------------------------------------------------------------------------
__global__ __launch_bounds__(256) void encoder_kernel(
    const float* __restrict__ x, float* __restrict__ outT, int nrows,
    const float* __restrict__ W0, const float* __restrict__ b0,
    const float* __restrict__ W1, const float* __restrict__ b1,
    const float* __restrict__ W2, const float* __restrict__ b2)
{
    const int k    = blockIdx.y;
    const int row0 = blockIdx.x * 64;
    const int tid  = threadIdx.x;
    const int o    = tid & 63;   // neuron
    const int rr   = tid >> 6;   // row phase 0..3

    __shared__ float smem[10240];
    float* xs  = smem;           // 2048 floats
    float* hs0 = smem + 2048;    // 4096
    float* hs1 = smem + 6144;    // 4096
    float* hs2 = smem;           // 4160, aliases xs+hs0 (dead by layer 2)

    for (int i = tid; i < 64 * SDIM; i += 256)
        xs[i] = x[(size_t)row0 * SDIM + i];
    __syncthreads();

    // ---- layer 0: 32 -> 64 ----
    {
        float2 w[SDIM / 2];
        const float* Wp = W0 + (size_t)k * SDIM * HID + o;
        #pragma unroll
        for (int i = 0; i < SDIM / 2; i++)
            w[i] = make_float2(Wp[(2 * i) * HID], Wp[(2 * i + 1) * HID]);
        const float bias = b0[k * HID + o];
        #pragma unroll 4
        for (int r = rr; r < 64; r += 4) {
            const float2* xr = reinterpret_cast<const float2*>(xs + r * SDIM);
            float2 acc = make_float2(0.f, 0.f);
            #pragma unroll
            for (int i = 0; i < SDIM / 2; i++) acc = ffma2(xr[i], w[i], acc);
            hs0[r * HID + o] = fmaxf(acc.x + acc.y + bias, 0.f);
        }
    }
    __syncthreads();

    // ---- layer 1: 64 -> 64 ----
    {
        float2 w[HID / 2];
        const float* Wp = W1 + (size_t)k * HID * HID + o;
        #pragma unroll
        for (int i = 0; i < HID / 2; i++)
            w[i] = make_float2(Wp[(2 * i) * HID], Wp[(2 * i + 1) * HID]);
        const float bias = b1[k * HID + o];
        #pragma unroll 4
        for (int r = rr; r < 64; r += 4) {
            const float2* hr = reinterpret_cast<const float2*>(hs0 + r * HID);
            float2 acc = make_float2(0.f, 0.f);
            #pragma unroll
            for (int i = 0; i < HID / 2; i++) acc = ffma2(hr[i], w[i], acc);
            hs1[r * HID + o] = fmaxf(acc.x + acc.y + bias, 0.f);
        }
    }
    __syncthreads();

    // ---- layer 2: 64 -> 64, stage into hs2 (padded 65) for transpose ----
    {
        float2 w[HID / 2];
        const float* Wp = W2 + (size_t)k * HID * HID + o;
        #pragma unroll
        for (int i = 0; i < HID / 2; i++)
            w[i] = make_float2(Wp[(2 * i) * HID], Wp[(2 * i + 1) * HID]);
        const float bias = b2[k * HID + o];
        #pragma unroll 4
        for (int r = rr; r < 64; r += 4) {
            const float2* hr = reinterpret_cast<const float2*>(hs1 + r * HID);
            float2 acc = make_float2(0.f, 0.f);
            #pragma unroll
            for (int i = 0; i < HID / 2; i++) acc = ffma2(hr[i], w[i], acc);
            hs2[r * 65 + o] = fmaxf(acc.x + acc.y + bias, 0.f);
        }
    }
    __syncthreads();

    // ---- coalesced transposed write: outT[k][d][row0+h] ----
    for (int i = tid; i < 64 * 64; i += 256) {
        int h = i & 63, d = i >> 6;
        outT[((size_t)k * HID + d) * nrows + row0 + h] = hs2[h * 65 + d];
    }
}

// ---------------------------------------------------------------------------
// V transpose: g_VT[a][j] = V[j][a]
// ---------------------------------------------------------------------------
__global__ __launch_bounds__(256) void vtrans_kernel(const float* __restrict__ V)
{
    __shared__ float sm[128 * GA];
    const int j0 = blockIdx.x * 128;
    for (int i = threadIdx.x; i < 128 * GA; i += 256)
        sm[i] = V[(size_t)j0 * GA + i];
    __syncthreads();
    for (int i = threadIdx.x; i < 128 * GA; i += 256) {
        int a = i >> 7, j = i & 127;
        g_VT[(size_t)a * NH + j0 + j] = sm[j * GA + a];
    }
}

// ---------------------------------------------------------------------------
// Flash attention, register-tiled, double-buffered cp.async.
// Block = (k, 32-query tile), 8 warps. Warp g owns queries 4g..4g+3.
// Scores: lane owns keys 4*lane..4*lane+3 (4q x 4k per thread, rank-1 over d).
// PV: lane = jh*16 + ah; thread owns 4q x 5a over its 64-key j-half.
// ---------------------------------------------------------------------------
__global__ __launch_bounds__(ATHREADS, 1) void attn_kernel()
{
    extern __shared__ float sm[];
    float* Qs = sm;                        // HID x QROW
    float* Ksb0 = Qs + HID * QROW;         // HID x KROW (double buffered)
    float* Ksb1 = Ksb0 + HID * KROW;
    float* Vsb0 = Ksb1 + HID * KROW;       // GA x KROW (double buffered)
    float* Vsb1 = Vsb0 + GA * KROW;
    float* Ps   = Vsb1 + GA * KROW;        // QT x KROW

    const int k    = blockIdx.y;
    const int q0   = blockIdx.x * QT;
    const int tid  = threadIdx.x;
    const int warp = tid >> 5;
    const int lane = tid & 31;
    const int ah   = lane & 15;
    const int jh   = lane >> 4;

    const float* Kg = g_enc_hT + (size_t)k * HID * NH;
    const float* Qg = g_enc_sT + (size_t)k * HID * NB;

    // Q tile (transposed [d][q]), float4 coalesced
    for (int i = tid; i < HID * (QT / 4); i += ATHREADS) {
        int d = i >> 3, c = i & 7;
        *(float4*)(Qs + d * QROW + c * 4) =
            *(const float4*)(Qg + (size_t)d * NB + q0 + c * 4);
    }

    // prologue prefetch tile 0
    {
        #pragma unroll
        for (int it = 0; it < 8; it++) {
            int idx = tid + it * ATHREADS;
            int r = idx >> 5, c = idx & 31;
            cp16(Ksb0 + r * KROW + c * 4, Kg + (size_t)r * NH + c * 4);
        }
        #pragma unroll
        for (int it = 0; it < 10; it++) {
            int idx = tid + it * ATHREADS;
            int r = idx >> 5, c = idx & 31;
            cp16(Vsb0 + r * KROW + c * 4, g_VT + (size_t)r * NH + c * 4);
        }
        asm volatile("cp.async.commit_group;");
    }

    float m[4], l[4];
    #pragma unroll
    for (int qi = 0; qi < 4; qi++) { m[qi] = -CUDART_INF_F; l[qi] = 0.f; }
    float2 oacc[4][5];
    #pragma unroll
    for (int qi = 0; qi < 4; qi++)
        #pragma unroll
        for (int a = 0; a < 5; a++) oacc[qi][a] = make_float2(0.f, 0.f);

    for (int t = 0; t < NTILES; t++) {
        float* Kc = (t & 1) ? Ksb1 : Ksb0;
        float* Vc = (t & 1) ? Vsb1 : Vsb0;

        if (t + 1 < NTILES) {
            const int key0 = (t + 1) * KT;
            float* Kn = (t & 1) ? Ksb0 : Ksb1;
            float* Vn = (t & 1) ? Vsb0 : Vsb1;
            #pragma unroll
            for (int it = 0; it < 8; it++) {
                int idx = tid + it * ATHREADS;
                int r = idx >> 5, c = idx & 31;
                cp16(Kn + r * KROW + c * 4, Kg + (size_t)r * NH + key0 + c * 4);
            }
            #pragma unroll
            for (int it = 0; it < 10; it++) {
                int idx = tid + it * ATHREADS;
                int r = idx >> 5, c = idx & 31;
                cp16(Vn + r * KROW + c * 4, g_VT + (size_t)r * NH + key0 + c * 4);
            }
            asm volatile("cp.async.commit_group;");
            asm volatile("cp.async.wait_group 1;");
        } else {
            asm volatile("cp.async.wait_group 0;");
        }
        __syncthreads();

        // ---- scores: 4q x 4k rank-1 over d; acc paired over k ----
        float2 aA[4], aB[4];
        #pragma unroll
        for (int qi = 0; qi < 4; qi++) {
            aA[qi] = make_float2(0.f, 0.f);
            aB[qi] = make_float2(0.f, 0.f);
        }
        const float* Kp = Kc + 4 * lane;
        const float* Qp = Qs + 4 * warp;
        #pragma unroll 8
        for (int d = 0; d < HID; d++) {
            float4 k4 = *(const float4*)(Kp + d * KROW);
            float4 q4 = *(const float4*)(Qp + d * QROW);
            float2 kA = make_float2(k4.x, k4.y);
            float2 kB = make_float2(k4.z, k4.w);
            float2 qd;
            qd = make_float2(q4.x, q4.x);
            aA[0] = ffma2(qd, kA, aA[0]); aB[0] = ffma2(qd, kB, aB[0]);
            qd = make_float2(q4.y, q4.y);
            aA[1] = ffma2(qd, kA, aA[1]); aB[1] = ffma2(qd, kB, aB[1]);
            qd = make_float2(q4.z, q4.z);
            aA[2] = ffma2(qd, kA, aA[2]); aB[2] = ffma2(qd, kB, aB[2]);
            qd = make_float2(q4.w, q4.w);
            aA[3] = ffma2(qd, kA, aA[3]); aB[3] = ffma2(qd, kB, aB[3]);
        }

        // ---- online softmax (full-warp: 128 keys per query) ----
        #pragma unroll
        for (int qi = 0; qi < 4; qi++) {
            float s0 = aA[qi].x, s1 = aA[qi].y, s2 = aB[qi].x, s3 = aB[qi].y;
            float mx = fmaxf(fmaxf(s0, s1), fmaxf(s2, s3));
            #pragma unroll
            for (int off = 16; off > 0; off >>= 1)
                mx = fmaxf(mx, __shfl_xor_sync(0xffffffffu, mx, off));
            float nm = fmaxf(m[qi], mx);
            float c = __expf(m[qi] - nm);
            m[qi] = nm;
            float p0 = __expf(s0 - nm), p1 = __expf(s1 - nm);
            float p2 = __expf(s2 - nm), p3 = __expf(s3 - nm);
            float ts = (p0 + p1) + (p2 + p3);
            #pragma unroll
            for (int off = 16; off > 0; off >>= 1)
                ts += __shfl_xor_sync(0xffffffffu, ts, off);
            l[qi] = l[qi] * c + ts;
            *(float4*)(Ps + (4 * warp + qi) * KROW + 4 * lane) =
                make_float4(p0, p1, p2, p3);
            #pragma unroll
            for (int a = 0; a < 5; a++) {
                oacc[qi][a].x *= c;
                oacc[qi][a].y *= c;
            }
        }
        __syncwarp();   // Ps rows are warp-private: warp-level sync suffices

        // ---- PV: 4q x 5a per thread over its 64-key half; paired over j ----
        const float* Pp = Ps + (4 * warp) * KROW + jh * 64;
        const float* Vp = Vc + (5 * ah) * KROW + jh * 64;
        #pragma unroll 4
        for (int j2 = 0; j2 < 32; j2++) {
            float2 p0 = *(const float2*)(Pp + 0 * KROW + 2 * j2);
            float2 p1 = *(const float2*)(Pp + 1 * KROW + 2 * j2);
            float2 p2 = *(const float2*)(Pp + 2 * KROW + 2 * j2);
            float2 p3 = *(const float2*)(Pp + 3 * KROW + 2 * j2);
            #pragma unroll
            for (int a = 0; a < 5; a++) {
                float2 v2 = *(const float2*)(Vp + a * KROW + 2 * j2);
                oacc[0][a] = ffma2(p0, v2, oacc[0][a]);
                oacc[1][a] = ffma2(p1, v2, oacc[1][a]);
                oacc[2][a] = ffma2(p2, v2, oacc[2][a]);
                oacc[3][a] = ffma2(p3, v2, oacc[3][a]);
            }
        }
        __syncthreads();   // all warps done with Kc/Vc before buffer reuse
    }

    // ---- epilogue: reduce j-halves, normalize, write ----
    #pragma unroll
    for (int qi = 0; qi < 4; qi++) {
        float inv = 1.0f / l[qi];
        #pragma unroll
        for (int a = 0; a < 5; a++) {
            float o = oacc[qi][a].x + oacc[qi][a].y;
            o += __shfl_xor_sync(0xffffffffu, o, 16);
            if (jh == 0)
                g_O[((size_t)k * NB + q0 + 4 * warp + qi) * GA + 5 * ah + a] =
                    o * inv;
        }
    }
}

// ---------------------------------------------------------------------------
// Combine: out[b,g,a] = sum_k softmax_k(assign[g,:]) * O[k,b,g*8+a]
// ---------------------------------------------------------------------------
__global__ __launch_bounds__(256) void combine_kernel(
    const float* __restrict__ assign, float* __restrict__ out)
{
    int idx = blockIdx.x * 256 + threadIdx.x;
    if (idx >= NB * GA) return;
    int b  = idx / GA;
    int ga = idx - b * GA;
    int g  = ga >> 3;
    float a0 = __ldg(assign + g * NK + 0);
    float a1 = __ldg(assign + g * NK + 1);
    float a2 = __ldg(assign + g * NK + 2);
    float a3 = __ldg(assign + g * NK + 3);
    float mx = fmaxf(fmaxf(a0, a1), fmaxf(a2, a3));
    float e0 = __expf(a0 - mx), e1 = __expf(a1 - mx);
    float e2 = __expf(a2 - mx), e3 = __expf(a3 - mx);
    float inv = 1.f / (e0 + e1 + e2 + e3);
    float r = e0 * g_O[(size_t)(0 * NB + b) * GA + ga]
            + e1 * g_O[(size_t)(1 * NB + b) * GA + ga]
            + e2 * g_O[(size_t)(2 * NB + b) * GA + ga]
            + e3 * g_O[(size_t)(3 * NB + b) * GA + ga];
    out[idx] = r * inv;
}

// ---------------------------------------------------------------------------
extern "C" void kernel_launch(void* const* d_in, const int* in_sizes, int n_in,
                              void* d_out, int out_size)
{
    (void)in_sizes; (void)n_in; (void)out_size;
    const float* state  = (const float*)d_in[0];
    const float* hist   = (const float*)d_in[1];
    const float* jah    = (const float*)d_in[2];
    const float* W0 = (const float*)d_in[3];
    const float* b0 = (const float*)d_in[4];
    const float* W1 = (const float*)d_in[5];
    const float* b1 = (const float*)d_in[6];
    const float* W2 = (const float*)d_in[7];
    const float* b2 = (const float*)d_in[8];
    const float* assign = (const float*)d_in[9];
    float* out = (float*)d_out;

    float* enc_hT_p = nullptr;
    float* enc_sT_p = nullptr;
    cudaGetSymbolAddress((void**)&enc_hT_p, g_enc_hT);
    cudaGetSymbolAddress((void**)&enc_sT_p, g_enc_sT);

    vtrans_kernel<<<NH / 128, 256>>>(jah);
    encoder_kernel<<<dim3(NH / 64, NK), 256>>>(hist, enc_hT_p, NH,
                                               W0, b0, W1, b1, W2, b2);
    encoder_kernel<<<dim3(NB / 64, NK), 256>>>(state, enc_sT_p, NB,
                                               W0, b0, W1, b1, W2, b2);

    const int smem_bytes =
        (HID * QROW + 2 * HID * KROW + 2 * GA * KROW + QT * KROW) *
        (int)sizeof(float);
    cudaFuncSetAttribute(attn_kernel,
                         cudaFuncAttributeMaxDynamicSharedMemorySize, smem_bytes);
    attn_kernel<<<dim3(NB / QT, NK), ATHREADS, smem_bytes>>>();

    combine_kernel<<<(NB * GA + 255) / 256, 256>>>(assign, out);
}

// round 6
// speedup vs baseline: 2.0795x; 1.1805x over previous
#include <cuda_runtime.h>
#include <math_constants.h>

#define NB   1024
#define NH   16384
#define SDIM 32
#define HID  64
#define NG   10
#define NK   4
#define GA   80

#define QT   64            // queries per block (8 per warp)
#define KT   128           // keys per tile
#define KROW 132           // padded row stride for K/V/P smem tiles
#define QROW 68            // padded row stride for Q tile
#define NSPLIT 2
#define KEYS_PER_CTA (NH / NSPLIT)      // 8192
#define NTILES (KEYS_PER_CTA / KT)      // 64
#define ATHREADS 256

// Scratch (no cudaMalloc allowed)
__device__ float g_enc_hT[NK * HID * NH];        // [k][d][h]
__device__ float g_enc_sT[NK * HID * NB];        // [k][d][b]
__device__ float g_VT[GA * NH];                  // [a][j]
__device__ float g_Opart[NSPLIT * NK * NB * GA]; // unnormalized partial O
__device__ float g_ml[NSPLIT * NK * NB * 2];     // (m, l) per split/k/row

// Packed dual-fp32 FMA / MUL (sm_103a f32x2 pipe)
__device__ __forceinline__ float2 ffma2(float2 a, float2 b, float2 c) {
    unsigned long long ua = *reinterpret_cast<unsigned long long*>(&a);
    unsigned long long ub = *reinterpret_cast<unsigned long long*>(&b);
    unsigned long long uc = *reinterpret_cast<unsigned long long*>(&c);
    unsigned long long ud;
    asm("fma.rn.f32x2 %0, %1, %2, %3;" : "=l"(ud) : "l"(ua), "l"(ub), "l"(uc));
    return *reinterpret_cast<float2*>(&ud);
}
__device__ __forceinline__ float2 fmul2(float2 a, float2 b) {
    unsigned long long ua = *reinterpret_cast<unsigned long long*>(&a);
    unsigned long long ub = *reinterpret_cast<unsigned long long*>(&b);
    unsigned long long ud;
    asm("mul.rn.f32x2 %0, %1, %2;" : "=l"(ud) : "l"(ua), "l"(ub));
    return *reinterpret_cast<float2*>(&ud);
}

__device__ __forceinline__ void cp16(float* dst, const float* src) {
    unsigned s = (unsigned)__cvta_generic_to_shared(dst);
    asm volatile("cp.async.cg.shared.global [%0], [%1], 16;\n" :: "r"(s), "l"(src));
}

// ---------------------------------------------------------------------------
// Encoder: x[nrows,32] -> outT[k][d][nrows] (TRANSPOSED), 3x (Linear+ReLU).
// ---------------------------------------------------------------------------
__global__ __launch_bounds__(256) void encoder_kernel(
    const float* __restrict__ x, float* __restrict__ outT, int nrows,
    const float* __restrict__ W0, const float* __restrict__ b0,
    const float* __restrict__ W1, const float* __restrict__ b1,
    const float* __restrict__ W2, const float* __restrict__ b2)
{
    const int k    = blockIdx.y;
    const int row0 = blockIdx.x * 64;
    const int tid  = threadIdx.x;
    const int o    = tid & 63;
    const int rr   = tid >> 6;

    __shared__ float smem[10240];
    float* xs  = smem;
    float* hs0 = smem + 2048;
    float* hs1 = smem + 6144;
    float* hs2 = smem;   // aliases xs+hs0 (dead by layer 2)

    for (int i = tid; i < 64 * SDIM; i += 256)
        xs[i] = x[(size_t)row0 * SDIM + i];
    __syncthreads();

    {
        float2 w[SDIM / 2];
        const float* Wp = W0 + (size_t)k * SDIM * HID + o;
        #pragma unroll
        for (int i = 0; i < SDIM / 2; i++)
            w[i] = make_float2(Wp[(2 * i) * HID], Wp[(2 * i + 1) * HID]);
        const float bias = b0[k * HID + o];
        #pragma unroll 4
        for (int r = rr; r < 64; r += 4) {
            const float2* xr = reinterpret_cast<const float2*>(xs + r * SDIM);
            float2 acc = make_float2(0.f, 0.f);
            #pragma unroll
            for (int i = 0; i < SDIM / 2; i++) acc = ffma2(xr[i], w[i], acc);
            hs0[r * HID + o] = fmaxf(acc.x + acc.y + bias, 0.f);
        }
    }
    __syncthreads();

    {
        float2 w[HID / 2];
        const float* Wp = W1 + (size_t)k * HID * HID + o;
        #pragma unroll
        for (int i = 0; i < HID / 2; i++)
            w[i] = make_float2(Wp[(2 * i) * HID], Wp[(2 * i + 1) * HID]);
        const float bias = b1[k * HID + o];
        #pragma unroll 4
        for (int r = rr; r < 64; r += 4) {
            const float2* hr = reinterpret_cast<const float2*>(hs0 + r * HID);
            float2 acc = make_float2(0.f, 0.f);
            #pragma unroll
            for (int i = 0; i < HID / 2; i++) acc = ffma2(hr[i], w[i], acc);
            hs1[r * HID + o] = fmaxf(acc.x + acc.y + bias, 0.f);
        }
    }
    __syncthreads();

    {
        float2 w[HID / 2];
        const float* Wp = W2 + (size_t)k * HID * HID + o;
        #pragma unroll
        for (int i = 0; i < HID / 2; i++)
            w[i] = make_float2(Wp[(2 * i) * HID], Wp[(2 * i + 1) * HID]);
        const float bias = b2[k * HID + o];
        #pragma unroll 4
        for (int r = rr; r < 64; r += 4) {
            const float2* hr = reinterpret_cast<const float2*>(hs1 + r * HID);
            float2 acc = make_float2(0.f, 0.f);
            #pragma unroll
            for (int i = 0; i < HID / 2; i++) acc = ffma2(hr[i], w[i], acc);
            hs2[r * 65 + o] = fmaxf(acc.x + acc.y + bias, 0.f);
        }
    }
    __syncthreads();

    for (int i = tid; i < 64 * 64; i += 256) {
        int h = i & 63, d = i >> 6;
        outT[((size_t)k * HID + d) * nrows + row0 + h] = hs2[h * 65 + d];
    }
}

// ---------------------------------------------------------------------------
// V transpose: g_VT[a][j] = V[j][a]
// ---------------------------------------------------------------------------
__global__ __launch_bounds__(256) void vtrans_kernel(const float* __restrict__ V)
{
    __shared__ float sm[128 * GA];
    const int j0 = blockIdx.x * 128;
    for (int i = threadIdx.x; i < 128 * GA; i += 256)
        sm[i] = V[(size_t)j0 * GA + i];
    __syncthreads();
    for (int i = threadIdx.x; i < 128 * GA; i += 256) {
        int a = i >> 7, j = i & 127;
        g_VT[(size_t)a * NH + j0 + j] = sm[j * GA + a];
    }
}

// ---------------------------------------------------------------------------
// Flash attention, split-K. Block = (qtile64, k, split). 8 warps x 8 queries.
// Scores: lane owns keys 4*lane..+3 (8q x 4k per thread, rank-1 over d).
// PV: lane = jh*16 + ah; 8q x 5a per thread over its 64-key j-half;
//     V read as deduped float4 (2-cyc floor), jh half selected in regs.
// Writes UNNORMALIZED partial O + (m,l) for the merge kernel.
// ---------------------------------------------------------------------------
__global__ __launch_bounds__(ATHREADS, 1) void attn_kernel()
{
    extern __shared__ float sm[];
    float* Qs   = sm;                      // HID x QROW
    float* Ksb0 = Qs + HID * QROW;         // HID x KROW (double buffered)
    float* Ksb1 = Ksb0 + HID * KROW;
    float* Vsb0 = Ksb1 + HID * KROW;       // GA x KROW (double buffered)
    float* Vsb1 = Vsb0 + GA * KROW;
    float* Ps   = Vsb1 + GA * KROW;        // QT x KROW

    const int k    = blockIdx.y;
    const int s    = blockIdx.z;
    const int q0   = blockIdx.x * QT;
    const int tid  = threadIdx.x;
    const int warp = tid >> 5;
    const int lane = tid & 31;
    const int ah   = lane & 15;
    const int jh   = lane >> 4;
    const int kb   = s * KEYS_PER_CTA;

    const float* Kg = g_enc_hT + (size_t)k * HID * NH;
    const float* Qg = g_enc_sT + (size_t)k * HID * NB;

    // Q tile [d][q], float4 coalesced
    for (int i = tid; i < HID * (QT / 4); i += ATHREADS) {
        int d = i >> 4, c = i & 15;
        *(float4*)(Qs + d * QROW + c * 4) =
            *(const float4*)(Qg + (size_t)d * NB + q0 + c * 4);
    }

    // prologue prefetch tile 0
    {
        #pragma unroll
        for (int it = 0; it < 8; it++) {
            int idx = tid + it * ATHREADS;
            int r = idx >> 5, c = idx & 31;
            cp16(Ksb0 + r * KROW + c * 4, Kg + (size_t)r * NH + kb + c * 4);
        }
        #pragma unroll
        for (int it = 0; it < 10; it++) {
            int idx = tid + it * ATHREADS;
            int r = idx >> 5, c = idx & 31;
            cp16(Vsb0 + r * KROW + c * 4, g_VT + (size_t)r * NH + kb + c * 4);
        }
        asm volatile("cp.async.commit_group;");
    }

    float m[8], l[8];
    #pragma unroll
    for (int qi = 0; qi < 8; qi++) { m[qi] = -CUDART_INF_F; l[qi] = 0.f; }
    float2 oacc[8][5];
    #pragma unroll
    for (int qi = 0; qi < 8; qi++)
        #pragma unroll
        for (int a = 0; a < 5; a++) oacc[qi][a] = make_float2(0.f, 0.f);

    for (int t = 0; t < NTILES; t++) {
        float* Kc = (t & 1) ? Ksb1 : Ksb0;
        float* Vc = (t & 1) ? Vsb1 : Vsb0;

        if (t + 1 < NTILES) {
            const int key0 = kb + (t + 1) * KT;
            float* Kn = (t & 1) ? Ksb0 : Ksb1;
            float* Vn = (t & 1) ? Vsb0 : Vsb1;
            #pragma unroll
            for (int it = 0; it < 8; it++) {
                int idx = tid + it * ATHREADS;
                int r = idx >> 5, c = idx & 31;
                cp16(Kn + r * KROW + c * 4, Kg + (size_t)r * NH + key0 + c * 4);
            }
            #pragma unroll
            for (int it = 0; it < 10; it++) {
                int idx = tid + it * ATHREADS;
                int r = idx >> 5, c = idx & 31;
                cp16(Vn + r * KROW + c * 4, g_VT + (size_t)r * NH + key0 + c * 4);
            }
            asm volatile("cp.async.commit_group;");
            asm volatile("cp.async.wait_group 1;");
        } else {
            asm volatile("cp.async.wait_group 0;");
        }
        __syncthreads();

        // ---- scores: 8q x 4k rank-1 over d; acc packed over key-pairs ----
        float2 aA[8], aB[8];
        #pragma unroll
        for (int qi = 0; qi < 8; qi++) {
            aA[qi] = make_float2(0.f, 0.f);
            aB[qi] = make_float2(0.f, 0.f);
        }
        const float* Kp = Kc + 4 * lane;
        const float* Qp = Qs + 8 * warp;
        #pragma unroll 4
        for (int d = 0; d < HID; d++) {
            float4 k4 = *(const float4*)(Kp + d * KROW);
            float4 qa = *(const float4*)(Qp + d * QROW);
            float4 qb = *(const float4*)(Qp + d * QROW + 4);
            float2 kA = make_float2(k4.x, k4.y);
            float2 kB = make_float2(k4.z, k4.w);
            float2 qd;
            qd = make_float2(qa.x, qa.x);
            aA[0] = ffma2(qd, kA, aA[0]); aB[0] = ffma2(qd, kB, aB[0]);
            qd = make_float2(qa.y, qa.y);
            aA[1] = ffma2(qd, kA, aA[1]); aB[1] = ffma2(qd, kB, aB[1]);
            qd = make_float2(qa.z, qa.z);
            aA[2] = ffma2(qd, kA, aA[2]); aB[2] = ffma2(qd, kB, aB[2]);
            qd = make_float2(qa.w, qa.w);
            aA[3] = ffma2(qd, kA, aA[3]); aB[3] = ffma2(qd, kB, aB[3]);
            qd = make_float2(qb.x, qb.x);
            aA[4] = ffma2(qd, kA, aA[4]); aB[4] = ffma2(qd, kB, aB[4]);
            qd = make_float2(qb.y, qb.y);
            aA[5] = ffma2(qd, kA, aA[5]); aB[5] = ffma2(qd, kB, aB[5]);
            qd = make_float2(qb.z, qb.z);
            aA[6] = ffma2(qd, kA, aA[6]); aB[6] = ffma2(qd, kB, aB[6]);
            qd = make_float2(qb.w, qb.w);
            aA[7] = ffma2(qd, kA, aA[7]); aB[7] = ffma2(qd, kB, aB[7]);
        }

        // ---- online softmax per query (warp-wide: 128 keys) ----
        #pragma unroll
        for (int qi = 0; qi < 8; qi++) {
            float s0 = aA[qi].x, s1 = aA[qi].y, s2 = aB[qi].x, s3 = aB[qi].y;
            float mx = fmaxf(fmaxf(s0, s1), fmaxf(s2, s3));
            #pragma unroll
            for (int off = 16; off > 0; off >>= 1)
                mx = fmaxf(mx, __shfl_xor_sync(0xffffffffu, mx, off));
            float nm = fmaxf(m[qi], mx);
            float c = __expf(m[qi] - nm);
            m[qi] = nm;
            float p0 = __expf(s0 - nm), p1 = __expf(s1 - nm);
            float p2 = __expf(s2 - nm), p3 = __expf(s3 - nm);
            float ts = (p0 + p1) + (p2 + p3);
            #pragma unroll
            for (int off = 16; off > 0; off >>= 1)
                ts += __shfl_xor_sync(0xffffffffu, ts, off);
            l[qi] = l[qi] * c + ts;
            *(float4*)(Ps + (8 * warp + qi) * KROW + 4 * lane) =
                make_float4(p0, p1, p2, p3);
            float2 cc = make_float2(c, c);
            #pragma unroll
            for (int a = 0; a < 5; a++) oacc[qi][a] = fmul2(oacc[qi][a], cc);
        }
        __syncwarp();   // Ps rows are warp-private

        // ---- PV: 8q x 5a per thread; V as deduped float4, jh-half in regs --
        const float* Pp = Ps + (8 * warp) * KROW + 2 * jh;
        const float* Vp = Vc + (5 * ah) * KROW;
        #pragma unroll 4
        for (int tt = 0; tt < 32; tt++) {
            float2 p[8];
            #pragma unroll
            for (int qi = 0; qi < 8; qi++)
                p[qi] = *(const float2*)(Pp + qi * KROW + 4 * tt);
            #pragma unroll
            for (int a = 0; a < 5; a++) {
                float4 v4 = *(const float4*)(Vp + a * KROW + 4 * tt);
                float2 vj = jh ? make_float2(v4.z, v4.w)
                               : make_float2(v4.x, v4.y);
                #pragma unroll
                for (int qi = 0; qi < 8; qi++)
                    oacc[qi][a] = ffma2(p[qi], vj, oacc[qi][a]);
            }
        }
        __syncthreads();   // all warps done with Kc/Vc before buffer reuse
    }

    // ---- epilogue: reduce jh halves, write UNNORMALIZED partials ----
    #pragma unroll
    for (int qi = 0; qi < 8; qi++) {
        const int row = q0 + 8 * warp + qi;
        float* Od = g_Opart + (((size_t)s * NK + k) * NB + row) * GA;
        #pragma unroll
        for (int a = 0; a < 5; a++) {
            float o = oacc[qi][a].x + oacc[qi][a].y;
            o += __shfl_xor_sync(0xffffffffu, o, 16);
            if (jh == 0) Od[5 * ah + a] = o;
        }
        if (lane == 0) {
            g_ml[(((size_t)s * NK + k) * NB + row) * 2 + 0] = m[qi];
            g_ml[(((size_t)s * NK + k) * NB + row) * 2 + 1] = l[qi];
        }
    }
}

// ---------------------------------------------------------------------------
// Merge: combine 2 key-splits (softmax merge) + k-combine in one pass.
// out[b,g,a] = sum_k softmax_k(assign[g,:]) * O_k[b,ga]
// ---------------------------------------------------------------------------
__global__ __launch_bounds__(256) void merge_kernel(
    const float* __restrict__ assign, float* __restrict__ out)
{
    int idx = blockIdx.x * 256 + threadIdx.x;
    if (idx >= NB * GA) return;
    int b  = idx / GA;
    int ga = idx - b * GA;
    int g  = ga >> 3;

    float aw[NK], mxw = -CUDART_INF_F;
    #pragma unroll
    for (int k = 0; k < NK; k++) {
        aw[k] = __ldg(assign + g * NK + k);
        mxw = fmaxf(mxw, aw[k]);
    }
    float wsum = 0.f;
    #pragma unroll
    for (int k = 0; k < NK; k++) {
        aw[k] = __expf(aw[k] - mxw);
        wsum += aw[k];
    }
    float winv = 1.f / wsum;

    float acc = 0.f;
    #pragma unroll
    for (int k = 0; k < NK; k++) {
        float m0 = g_ml[(((size_t)0 * NK + k) * NB + b) * 2 + 0];
        float l0 = g_ml[(((size_t)0 * NK + k) * NB + b) * 2 + 1];
        float m1 = g_ml[(((size_t)1 * NK + k) * NB + b) * 2 + 0];
        float l1 = g_ml[(((size_t)1 * NK + k) * NB + b) * 2 + 1];
        float M  = fmaxf(m0, m1);
        float w0 = __expf(m0 - M), w1 = __expf(m1 - M);
        float L  = l0 * w0 + l1 * w1;
        float O0 = g_Opart[(((size_t)0 * NK + k) * NB + b) * GA + ga];
        float O1 = g_Opart[(((size_t)1 * NK + k) * NB + b) * GA + ga];
        acc += aw[k] * ((O0 * w0 + O1 * w1) / L);
    }
    out[idx] = acc * winv;
}

// ---------------------------------------------------------------------------
extern "C" void kernel_launch(void* const* d_in, const int* in_sizes, int n_in,
                              void* d_out, int out_size)
{
    (void)in_sizes; (void)n_in; (void)out_size;
    const float* state  = (const float*)d_in[0];
    const float* hist   = (const float*)d_in[1];
    const float* jah    = (const float*)d_in[2];
    const float* W0 = (const float*)d_in[3];
    const float* b0 = (const float*)d_in[4];
    const float* W1 = (const float*)d_in[5];
    const float* b1 = (const float*)d_in[6];
    const float* W2 = (const float*)d_in[7];
    const float* b2 = (const float*)d_in[8];
    const float* assign = (const float*)d_in[9];
    float* out = (float*)d_out;

    float* enc_hT_p = nullptr;
    float* enc_sT_p = nullptr;
    cudaGetSymbolAddress((void**)&enc_hT_p, g_enc_hT);
    cudaGetSymbolAddress((void**)&enc_sT_p, g_enc_sT);

    vtrans_kernel<<<NH / 128, 256>>>(jah);
    encoder_kernel<<<dim3(NH / 64, NK), 256>>>(hist, enc_hT_p, NH,
                                               W0, b0, W1, b1, W2, b2);
    encoder_kernel<<<dim3(NB / 64, NK), 256>>>(state, enc_sT_p, NB,
                                               W0, b0, W1, b1, W2, b2);

    const int smem_bytes =
        (HID * QROW + 2 * HID * KROW + 2 * GA * KROW + QT * KROW) *
        (int)sizeof(float);
    cudaFuncSetAttribute(attn_kernel,
                         cudaFuncAttributeMaxDynamicSharedMemorySize, smem_bytes);
    attn_kernel<<<dim3(NB / QT, NK, NSPLIT), ATHREADS, smem_bytes>>>();

    merge_kernel<<<(NB * GA + 255) / 256, 256>>>(assign, out);
}